// round 10
// baseline (speedup 1.0000x reference)
#include <cuda_runtime.h>
#include <math.h>
#include <stdint.h>

#define D     1024
#define B     16
#define T     1024
#define G     128      // persistent CTAs (one per SM)
#define DPC   16       // d's per CTA
#define BPC   8        // b's per CTA
#define NTHR  512      // 16 warps: 2 d-groups (8d) x 8 k-slices (128k)

#define MAXR  0.999f
#define EPSF  1e-8f

typedef unsigned long long u64;

// ---------------- device scratch ----------------
__device__ float    g_hbuf[2][B * D];   // ping-pong hidden state
__device__ unsigned g_flag[2][64];      // per-half, per-CTA step flags
__device__ float    g_u[D], g_v[D];     // power-iteration vectors (raw)
__device__ float    g_nu[4], g_nv[4];   // sumsq accumulators per iteration
__device__ float    g_sig_acc;          // sigma accumulator (signed)

// ---------------- packed fp32x2 helpers ----------------
__device__ __forceinline__ u64 dup2(float w) {
    u64 r; asm("mov.b64 %0, {%1, %1};" : "=l"(r) : "f"(w)); return r;
}
__device__ __forceinline__ u64 pack2(float lo, float hi) {
    u64 r; asm("mov.b64 %0, {%1, %2};" : "=l"(r) : "f"(lo), "f"(hi)); return r;
}
__device__ __forceinline__ void fma2(u64& a, u64 w, u64 x) {
    asm("fma.rn.f32x2 %0, %1, %2, %0;" : "+l"(a) : "l"(w), "l"(x));
}
__device__ __forceinline__ u64 addp(u64 a, u64 b) {
    u64 c; asm("add.rn.f32x2 %0, %1, %2;" : "=l"(c) : "l"(a), "l"(b)); return c;
}
__device__ __forceinline__ float lo32(u64 a) { return __uint_as_float((unsigned)(a & 0xffffffffull)); }
__device__ __forceinline__ float hi32(u64 a) { return __uint_as_float((unsigned)(a >> 32)); }

// coherent L2 scalar load (cross-SM mutable data)
__device__ __forceinline__ float ldcg(const float* p) {
    float v; asm volatile("ld.global.cg.f32 %0, [%1];" : "=f"(v) : "l"(p)); return v;
}
// acquire / release flag ops
__device__ __forceinline__ unsigned lda(const unsigned* p) {
    unsigned v;
    asm volatile("ld.acquire.gpu.global.b32 %0, [%1];" : "=r"(v) : "l"(p) : "memory");
    return v;
}
__device__ __forceinline__ void strel(unsigned* p, unsigned v) {
    asm volatile("st.release.gpu.global.b32 [%0], %1;" :: "l"(p), "r"(v) : "memory");
}

// ---------------- init: reset flags/accumulators, write h_all[0] ----------------
__global__ void k_init(const float* __restrict__ h0, float* __restrict__ hall0) {
    int i = blockIdx.x * blockDim.x + threadIdx.x;
    if (i < 128) ((unsigned*)g_flag)[i] = 0u;
    if (i < 4) { g_nu[i] = 0.f; g_nv[i] = 0.f; }
    if (i == 4) g_sig_acc = 0.f;
    if (i < B * D) hall0[i] = h0[i];
}

// ---------------- power iteration: distributed kernels ----------------
__global__ void k_dot(const float* __restrict__ u0) {   // <<<1, 1024>>>
    __shared__ float sred[32];
    int tid = threadIdx.x;
    float v = u0[tid];
    g_u[tid] = v;
    float s = v * v;
#pragma unroll
    for (int m = 16; m; m >>= 1) s += __shfl_xor_sync(0xffffffffu, s, m);
    if ((tid & 31) == 0) sred[tid >> 5] = s;
    __syncthreads();
    if (tid < 32) {
        float r = sred[tid];
#pragma unroll
        for (int m = 16; m; m >>= 1) r += __shfl_xor_sync(0xffffffffu, r, m);
        if (tid == 0) g_nu[0] = r;
    }
}

// v_raw = Wh^T * normalize(u_raw) ; accumulate sumsq(v_raw) -> g_nv[p]   <<<16, 64>>>
__global__ void k_mvT(const float* __restrict__ Wh, int p) {
    __shared__ float us[D];
    __shared__ float w2[2];
    int i = blockIdx.x * 64 + threadIdx.x;
    float rs = 1.f / (sqrtf(g_nu[p]) + EPSF);
    for (int j = threadIdx.x; j < D; j += 64) us[j] = g_u[j] * rs;
    __syncthreads();
    float acc = 0.f;
#pragma unroll 8
    for (int j = 0; j < D; ++j) acc += Wh[(size_t)j * D + i] * us[j];
    g_v[i] = acc;
    float s = acc * acc;
#pragma unroll
    for (int m = 16; m; m >>= 1) s += __shfl_xor_sync(0xffffffffu, s, m);
    if ((threadIdx.x & 31) == 0) w2[threadIdx.x >> 5] = s;
    __syncthreads();
    if (threadIdx.x == 0) atomicAdd(&g_nv[p], w2[0] + w2[1]);
}

// u_raw = Wh * normalize(v_raw) ; accumulate sumsq(u_raw) -> g_nu[p+1]   <<<128, 256>>>
__global__ void k_mvN(const float* __restrict__ Wh, int p) {
    __shared__ float part[8];
    int wid = threadIdx.x >> 5, lane = threadIdx.x & 31;
    int r = blockIdx.x * 8 + wid;
    float rs = 1.f / (sqrtf(g_nv[p]) + EPSF);
    const float* row = Wh + (size_t)r * D;
    float acc = 0.f;
#pragma unroll
    for (int i = 0; i < 32; ++i) { int j = lane + 32 * i; acc += row[j] * g_v[j]; }
#pragma unroll
    for (int m = 16; m; m >>= 1) acc += __shfl_xor_sync(0xffffffffu, acc, m);
    if (lane == 0) { float u = acc * rs; g_u[r] = u; part[wid] = u * u; }
    __syncthreads();
    if (threadIdx.x == 0) {
        float s = 0.f;
#pragma unroll
        for (int q = 0; q < 8; ++q) s += part[q];
        atomicAdd(&g_nu[p + 1], s);
    }
}

// sigma = sum_r normalize(u)_r * (Wh * normalize(v))_r   <<<128, 256>>>
__global__ void k_sigma(const float* __restrict__ Wh) {
    __shared__ float part[8];
    int wid = threadIdx.x >> 5, lane = threadIdx.x & 31;
    int r = blockIdx.x * 8 + wid;
    float rsv = 1.f / (sqrtf(g_nv[2]) + EPSF);
    float rsu = 1.f / (sqrtf(g_nu[3]) + EPSF);
    const float* row = Wh + (size_t)r * D;
    float acc = 0.f;
#pragma unroll
    for (int i = 0; i < 32; ++i) { int j = lane + 32 * i; acc += row[j] * g_v[j]; }
#pragma unroll
    for (int m = 16; m; m >>= 1) acc += __shfl_xor_sync(0xffffffffu, acc, m);
    if (lane == 0) part[wid] = (g_u[r] * rsu) * (acc * rsv);
    __syncthreads();
    if (threadIdx.x == 0) {
        float s = 0.f;
#pragma unroll
        for (int q = 0; q < 8; ++q) s += part[q];
        atomicAdd(&g_sig_acc, s);
    }
}

// ---------------- GEMV tiles: 8d x 8b per warp, 128 k ----------------
// x from GMEM (immutable input)
__device__ __forceinline__ void mv_x(const float* __restrict__ W,
                                     const float* __restrict__ V,
                                     u64* __restrict__ acc,
                                     int dbase, int kbase, int lane) {
#pragma unroll
    for (int i = 0; i < 4; ++i) {
        const int k = kbase + 32 * i + lane;
        float v0 = __ldg(V + 0 * D + k), v1 = __ldg(V + 1 * D + k);
        float v2 = __ldg(V + 2 * D + k), v3 = __ldg(V + 3 * D + k);
        float v4 = __ldg(V + 4 * D + k), v5 = __ldg(V + 5 * D + k);
        float v6 = __ldg(V + 6 * D + k), v7 = __ldg(V + 7 * D + k);
        u64 x0 = pack2(v0, v1), x1 = pack2(v2, v3);
        u64 x2 = pack2(v4, v5), x3 = pack2(v6, v7);
#pragma unroll
        for (int dd = 0; dd < 8; ++dd) {
            u64 w = dup2(W[(dbase + dd) * D + k]);
            fma2(acc[dd * 4 + 0], w, x0);
            fma2(acc[dd * 4 + 1], w, x1);
            fma2(acc[dd * 4 + 2], w, x2);
            fma2(acc[dd * 4 + 3], w, x3);
        }
    }
}

// h from GMEM via coherent L2 (cross-SM mutable)
__device__ __forceinline__ void mv_h(const float* __restrict__ W,
                                     const float* __restrict__ V,
                                     u64* __restrict__ acc,
                                     int dbase, int kbase, int lane) {
#pragma unroll
    for (int i = 0; i < 4; ++i) {
        const int k = kbase + 32 * i + lane;
        float v0 = ldcg(V + 0 * D + k), v1 = ldcg(V + 1 * D + k);
        float v2 = ldcg(V + 2 * D + k), v3 = ldcg(V + 3 * D + k);
        float v4 = ldcg(V + 4 * D + k), v5 = ldcg(V + 5 * D + k);
        float v6 = ldcg(V + 6 * D + k), v7 = ldcg(V + 7 * D + k);
        u64 x0 = pack2(v0, v1), x1 = pack2(v2, v3);
        u64 x2 = pack2(v4, v5), x3 = pack2(v6, v7);
#pragma unroll
        for (int dd = 0; dd < 8; ++dd) {
            u64 w = dup2(W[(dbase + dd) * D + k]);
            fma2(acc[dd * 4 + 0], w, x0);
            fma2(acc[dd * 4 + 1], w, x1);
            fma2(acc[dd * 4 + 2], w, x2);
            fma2(acc[dd * 4 + 3], w, x3);
        }
    }
}

// distributing tree reduce: lane L ends owning sum-over-lanes of acc[L]
#define RED_LEVEL(m, n)                                                     \
    {                                                                       \
        const bool up = (lane & (m)) != 0;                                  \
        _Pragma("unroll")                                                   \
        for (int j = 0; j < (n); ++j) {                                     \
            u64 send = up ? acc[j] : acc[j + (n)];                          \
            u64 recv = __shfl_xor_sync(0xffffffffu, send, (m));             \
            acc[j] = addp(up ? acc[j + (n)] : acc[j], recv);                \
        }                                                                   \
    }

// ---------------- persistent fused recurrence ----------------
__global__ void __launch_bounds__(NTHR, 1)
k_persist(const float* __restrict__ x, const float* __restrict__ z,
          const float* __restrict__ h0, const float* __restrict__ Wx,
          const float* __restrict__ Wh, const float* __restrict__ logr,
          const float* __restrict__ bias, float* __restrict__ out) {
    extern __shared__ float sm[];
    float* Wx_s  = sm;                       // [DPC][D]  64 KB
    float* Wh_s  = Wx_s + DPC * D;           // [DPC][D]  64 KB (pre-scaled)
    u64*   red_s = (u64*)(Wh_s + DPC * D);   // [8][64]    4 KB

    const int cta = blockIdx.x;
    const int d0 = (cta >> 1) * DPC;
    const int bg = cta & 1;                  // batch-half group
    const int b0 = bg * BPC;
    const int tid = threadIdx.x;
    const int wid = tid >> 5;                // 0..15
    const int lane = tid & 31;
    const int dg = wid >> 3;                 // d-group 0/1
    const int ks = wid & 7;                  // k-slice 0..7
    const int dbase = dg * 8;
    const int kbase = ks * 128;

    // ---- load weight tiles; pre-scale W_h rows by radii[d]/(sigma+eps) ----
    const float sig = fabsf(g_sig_acc) + EPSF;
    for (int i = tid; i < DPC * D / 4; i += NTHR) {
        int idx = i * 4;
        int dd = idx >> 10;
        int k = idx & (D - 1);
        int dglob = d0 + dd;
        *(float4*)(Wx_s + dd * D + k) = *(const float4*)(Wx + (size_t)dglob * D + k);
        float r = (MAXR / (1.f + expf(-logr[dglob]))) / sig;
        float4 m = *(const float4*)(Wh + (size_t)dglob * D + k);
        m.x *= r; m.y *= r; m.z *= r; m.w *= r;
        *(float4*)(Wh_s + dd * D + k) = m;
    }
    __syncthreads();   // weights visible to all warps before any smem-weight read

    float* outs_ptr = out;                        // [T][B][D]
    float* hall_ptr = out + (size_t)T * B * D;    // [T+1][B][D]

    // epilogue mapping (tid < 128): consecutive tid -> consecutive d
    const int dl = tid & 15;
    const int bl = (tid >> 4) & 7;
    const size_t eoff = (size_t)(b0 + bl) * D + (d0 + dl);
    const float my_bias = bias[d0 + dl];
    const int epi_p = (dl >> 3) * 32 + (dl & 7) * 4 + (bl >> 1);
    const int epi_half = bl & 1;

    u64 acc[32];

    // ---- step 0 x-part (independent of h) ----
#pragma unroll
    for (int i = 0; i < 32; ++i) acc[i] = 0ull;
    mv_x(Wx_s, x + (size_t)b0 * D, acc, dbase, kbase, lane);
    float zreg = (tid < 128) ? __ldg(z + eoff) : 0.f;

    for (int t = 0; t < T; ++t) {
        // ---- per-warp acquire-poll on the 64 flags of this batch-half ----
        if (t > 0) {
            const unsigned tgt = (unsigned)t;
            unsigned a, b;
            do {
                a = lda(&g_flag[bg][lane]);
                b = lda(&g_flag[bg][lane + 32]);
            } while (__any_sync(0xffffffffu, (a < tgt) | (b < tgt)));
            __syncwarp();
        }

        // ---- recurrent GEMV straight from L2: acc += W_heff * h_prev ----
        const float* hsrc = ((t == 0) ? h0 : g_hbuf[(t - 1) & 1]) + (size_t)b0 * D;
        mv_h(Wh_s, hsrc, acc, dbase, kbase, lane);

        // ---- tree reduce: lane L owns acc[L] ----
        RED_LEVEL(16, 16)
        RED_LEVEL(8, 8)
        RED_LEVEL(4, 4)
        RED_LEVEL(2, 2)
        RED_LEVEL(1, 1)
        red_s[ks * 64 + dg * 32 + lane] = acc[0];
        __syncthreads();   // sole CTA-wide sync per step (also guards h ping-pong)

        // ---- epilogue (warps 0-3): sum k-slices, tanh, publish, gate, arrive ----
        if (tid < 128) {
            u64 s0 = addp(red_s[0 * 64 + epi_p], red_s[1 * 64 + epi_p]);
            u64 s1 = addp(red_s[2 * 64 + epi_p], red_s[3 * 64 + epi_p]);
            u64 s2 = addp(red_s[4 * 64 + epi_p], red_s[5 * 64 + epi_p]);
            u64 s3 = addp(red_s[6 * 64 + epi_p], red_s[7 * 64 + epi_p]);
            u64 s = addp(addp(s0, s1), addp(s2, s3));
            float pre = (epi_half ? hi32(s) : lo32(s)) + my_bias;
            float hnew = tanhf(pre);
            g_hbuf[t & 1][eoff] = hnew;
            float sil = zreg / (1.f + __expf(-zreg));
            outs_ptr[(size_t)t * B * D + eoff] = hnew * sil;
            hall_ptr[(size_t)(t + 1) * B * D + eoff] = hnew;
            asm volatile("bar.sync 1, 128;" ::: "memory");   // epi warps only
            if (tid == 0) strel(&g_flag[bg][cta >> 1], (unsigned)(t + 1));
        }

        // ---- shadow: x-part of step t+1 (overlaps other CTAs' epilogues) ----
#pragma unroll
        for (int i = 0; i < 32; ++i) acc[i] = 0ull;
        if (t + 1 < T) {
            mv_x(Wx_s, x + (size_t)(t + 1) * B * D + (size_t)b0 * D,
                 acc, dbase, kbase, lane);
            if (tid < 128) zreg = __ldg(z + (size_t)(t + 1) * B * D + eoff);
        }
    }
}

// ---------------- launch ----------------
extern "C" void kernel_launch(void* const* d_in, const int* in_sizes, int n_in,
                              void* d_out, int out_size) {
    const float* x    = (const float*)d_in[0];
    const float* z    = (const float*)d_in[1];
    const float* h0   = (const float*)d_in[2];
    const float* Wx   = (const float*)d_in[3];
    const float* Wh   = (const float*)d_in[4];
    const float* logr = (const float*)d_in[5];
    const float* bias = (const float*)d_in[6];
    const float* u0   = (const float*)d_in[7];
    float* out = (float*)d_out;

    const int smem_bytes = 2 * DPC * D * (int)sizeof(float) + 512 * (int)sizeof(u64);
    cudaFuncSetAttribute(k_persist, cudaFuncAttributeMaxDynamicSharedMemorySize,
                         smem_bytes);

    k_init<<<64, 256>>>(h0, out + (size_t)T * B * D);
    k_dot<<<1, 1024>>>(u0);
    for (int p = 0; p < 3; ++p) {
        k_mvT<<<16, 64>>>(Wh, p);
        k_mvN<<<128, 256>>>(Wh, p);
    }
    k_sigma<<<128, 256>>>(Wh);
    k_persist<<<G, NTHR, smem_bytes>>>(x, z, h0, Wx, Wh, logr, bias, out);
}

// round 13
// speedup vs baseline: 1.1852x; 1.1852x over previous
#include <cuda_runtime.h>
#include <math.h>
#include <stdint.h>

#define D     1024
#define B     16
#define T     1024
#define G     128      // persistent CTAs (one per SM)
#define HALF  64       // CTAs per batch-half barrier group
#define DPC   16       // d's per CTA
#define BPC   8        // b's per CTA
#define NTHR  512      // 16 warps: 2 d-groups (8d) x 8 k-slices (128k)

#define MAXR  0.999f
#define EPSF  1e-8f

typedef unsigned long long u64;

// ---------------- device scratch ----------------
__device__ float    g_pre[T * B * D];   // 64 MB precomputed x-part (+bias)
__device__ float    g_hbuf[2][B * D];   // ping-pong hidden state
__device__ unsigned g_bar[2];           // one barrier per batch-half
__device__ float    g_u[D], g_v[D];     // power-iteration vectors (raw)
__device__ float    g_nu[4], g_nv[4];   // sumsq accumulators
__device__ float    g_sig_acc;          // sigma accumulator

// ---------------- packed fp32x2 helpers ----------------
__device__ __forceinline__ u64 dup2(float w) {
    u64 r; asm("mov.b64 %0, {%1, %1};" : "=l"(r) : "f"(w)); return r;
}
__device__ __forceinline__ u64 pack2(float lo, float hi) {
    u64 r; asm("mov.b64 %0, {%1, %2};" : "=l"(r) : "f"(lo), "f"(hi)); return r;
}
__device__ __forceinline__ void fma2(u64& a, u64 w, u64 x) {
    asm("fma.rn.f32x2 %0, %1, %2, %0;" : "+l"(a) : "l"(w), "l"(x));
}
__device__ __forceinline__ u64 addp(u64 a, u64 b) {
    u64 c; asm("add.rn.f32x2 %0, %1, %2;" : "=l"(c) : "l"(a), "l"(b)); return c;
}
__device__ __forceinline__ float lo32(u64 a) { return __uint_as_float((unsigned)(a & 0xffffffffull)); }
__device__ __forceinline__ float hi32(u64 a) { return __uint_as_float((unsigned)(a >> 32)); }

__device__ __forceinline__ float4 ldcg4(const float4* p) {
    float4 v;
    asm volatile("ld.global.cg.v4.f32 {%0,%1,%2,%3}, [%4];"
                 : "=f"(v.x), "=f"(v.y), "=f"(v.z), "=f"(v.w) : "l"(p));
    return v;
}
__device__ __forceinline__ float ldcg(const float* p) {
    float v; asm volatile("ld.global.cg.f32 %0, [%1];" : "=f"(v) : "l"(p)); return v;
}

// ---------------- init ----------------
__global__ void k_init(const float* __restrict__ h0, float* __restrict__ hall0) {
    int i = blockIdx.x * blockDim.x + threadIdx.x;
    if (i < 2) g_bar[i] = 0u;
    if (i < 4) { g_nu[i] = 0.f; g_nv[i] = 0.f; }
    if (i == 4) g_sig_acc = 0.f;
    if (i < B * D) hall0[i] = h0[i];
}

// ---------------- power iteration (distributed, proven in R9) ----------------
__global__ void k_dot(const float* __restrict__ u0) {   // <<<1, 1024>>>
    __shared__ float sred[32];
    int tid = threadIdx.x;
    float v = u0[tid];
    g_u[tid] = v;
    float s = v * v;
#pragma unroll
    for (int m = 16; m; m >>= 1) s += __shfl_xor_sync(0xffffffffu, s, m);
    if ((tid & 31) == 0) sred[tid >> 5] = s;
    __syncthreads();
    if (tid < 32) {
        float r = sred[tid];
#pragma unroll
        for (int m = 16; m; m >>= 1) r += __shfl_xor_sync(0xffffffffu, r, m);
        if (tid == 0) g_nu[0] = r;
    }
}

__global__ void k_mvT(const float* __restrict__ Wh, int p) {   // <<<16, 64>>>
    __shared__ float us[D];
    __shared__ float w2[2];
    int i = blockIdx.x * 64 + threadIdx.x;
    float rs = 1.f / (sqrtf(g_nu[p]) + EPSF);
    for (int j = threadIdx.x; j < D; j += 64) us[j] = g_u[j] * rs;
    __syncthreads();
    float acc = 0.f;
#pragma unroll 8
    for (int j = 0; j < D; ++j) acc += Wh[(size_t)j * D + i] * us[j];
    g_v[i] = acc;
    float s = acc * acc;
#pragma unroll
    for (int m = 16; m; m >>= 1) s += __shfl_xor_sync(0xffffffffu, s, m);
    if ((threadIdx.x & 31) == 0) w2[threadIdx.x >> 5] = s;
    __syncthreads();
    if (threadIdx.x == 0) atomicAdd(&g_nv[p], w2[0] + w2[1]);
}

__global__ void k_mvN(const float* __restrict__ Wh, int p) {   // <<<128, 256>>>
    __shared__ float part[8];
    int wid = threadIdx.x >> 5, lane = threadIdx.x & 31;
    int r = blockIdx.x * 8 + wid;
    float rs = 1.f / (sqrtf(g_nv[p]) + EPSF);
    const float* row = Wh + (size_t)r * D;
    float acc = 0.f;
#pragma unroll
    for (int i = 0; i < 32; ++i) { int j = lane + 32 * i; acc += row[j] * g_v[j]; }
#pragma unroll
    for (int m = 16; m; m >>= 1) acc += __shfl_xor_sync(0xffffffffu, acc, m);
    if (lane == 0) { float u = acc * rs; g_u[r] = u; part[wid] = u * u; }
    __syncthreads();
    if (threadIdx.x == 0) {
        float s = 0.f;
#pragma unroll
        for (int q = 0; q < 8; ++q) s += part[q];
        atomicAdd(&g_nu[p + 1], s);
    }
}

__global__ void k_sigma(const float* __restrict__ Wh) {   // <<<128, 256>>>
    __shared__ float part[8];
    int wid = threadIdx.x >> 5, lane = threadIdx.x & 31;
    int r = blockIdx.x * 8 + wid;
    float rsv = 1.f / (sqrtf(g_nv[2]) + EPSF);
    float rsu = 1.f / (sqrtf(g_nu[3]) + EPSF);
    const float* row = Wh + (size_t)r * D;
    float acc = 0.f;
#pragma unroll
    for (int i = 0; i < 32; ++i) { int j = lane + 32 * i; acc += row[j] * g_v[j]; }
#pragma unroll
    for (int m = 16; m; m >>= 1) acc += __shfl_xor_sync(0xffffffffu, acc, m);
    if (lane == 0) part[wid] = (g_u[r] * rsu) * (acc * rsv);
    __syncthreads();
    if (threadIdx.x == 0) {
        float s = 0.f;
#pragma unroll
        for (int q = 0; q < 8; ++q) s += part[q];
        atomicAdd(&g_sig_acc, s);
    }
}

// ---------------- GEMV tiles: 8d x 8b per warp, 128 k ----------------
__device__ __forceinline__ void mv_x(const float* __restrict__ W,
                                     const float* __restrict__ V,   // gmem [b][D]
                                     u64* __restrict__ acc,
                                     int dbase, int kbase, int lane) {
#pragma unroll
    for (int i = 0; i < 4; ++i) {
        const int k = kbase + 32 * i + lane;
        float v0 = __ldg(V + 0 * D + k), v1 = __ldg(V + 1 * D + k);
        float v2 = __ldg(V + 2 * D + k), v3 = __ldg(V + 3 * D + k);
        float v4 = __ldg(V + 4 * D + k), v5 = __ldg(V + 5 * D + k);
        float v6 = __ldg(V + 6 * D + k), v7 = __ldg(V + 7 * D + k);
        u64 x0 = pack2(v0, v1), x1 = pack2(v2, v3);
        u64 x2 = pack2(v4, v5), x3 = pack2(v6, v7);
#pragma unroll
        for (int dd = 0; dd < 8; ++dd) {
            u64 w = dup2(W[(dbase + dd) * D + k]);
            fma2(acc[dd * 4 + 0], w, x0);
            fma2(acc[dd * 4 + 1], w, x1);
            fma2(acc[dd * 4 + 2], w, x2);
            fma2(acc[dd * 4 + 3], w, x3);
        }
    }
}

__device__ __forceinline__ void mv_smem(const float* __restrict__ W,
                                        const float* __restrict__ V,   // smem [BPC][D]
                                        u64* __restrict__ acc,
                                        int dbase, int kbase, int lane) {
#pragma unroll
    for (int i = 0; i < 4; ++i) {
        const int k = kbase + 32 * i + lane;
        u64 x0 = pack2(V[0 * D + k], V[1 * D + k]);
        u64 x1 = pack2(V[2 * D + k], V[3 * D + k]);
        u64 x2 = pack2(V[4 * D + k], V[5 * D + k]);
        u64 x3 = pack2(V[6 * D + k], V[7 * D + k]);
#pragma unroll
        for (int dd = 0; dd < 8; ++dd) {
            u64 w = dup2(W[(dbase + dd) * D + k]);
            fma2(acc[dd * 4 + 0], w, x0);
            fma2(acc[dd * 4 + 1], w, x1);
            fma2(acc[dd * 4 + 2], w, x2);
            fma2(acc[dd * 4 + 3], w, x3);
        }
    }
}

#define RED_LEVEL(m, n)                                                     \
    {                                                                       \
        const bool up = (lane & (m)) != 0;                                  \
        _Pragma("unroll")                                                   \
        for (int j = 0; j < (n); ++j) {                                     \
            u64 send = up ? acc[j] : acc[j + (n)];                          \
            u64 recv = __shfl_xor_sync(0xffffffffu, send, (m));             \
            acc[j] = addp(up ? acc[j + (n)] : acc[j], recv);                \
        }                                                                   \
    }

#define RED_ALL() RED_LEVEL(16,16) RED_LEVEL(8,8) RED_LEVEL(4,4) RED_LEVEL(2,2) RED_LEVEL(1,1)

// ---------------- persistent fused kernel: phase A (pre-GEMM) + phase B (recurrence) ----------------
__global__ void __launch_bounds__(NTHR, 1)
k_persist(const float* __restrict__ x, const float* __restrict__ z,
          const float* __restrict__ h0, const float* __restrict__ Wx,
          const float* __restrict__ Wh, const float* __restrict__ logr,
          const float* __restrict__ bias, float* __restrict__ out) {
    extern __shared__ float sm[];
    float* Wx_s  = sm;                      // [DPC][D]  64 KB
    float* Wh_s  = Wx_s + DPC * D;          // [DPC][D]  64 KB (pre-scaled)
    float* h_s   = Wh_s + DPC * D;          // [BPC][D]  32 KB
    u64*   red_s = (u64*)(h_s + BPC * D);   // [2][8][64] 8 KB (double-buffered)

    const int cta = blockIdx.x;
    const int d0 = (cta >> 1) * DPC;
    const int bg = cta & 1;                 // batch-half group
    const int b0 = bg * BPC;
    const int tid = threadIdx.x;
    const int wid = tid >> 5;
    const int lane = tid & 31;
    const int dg = wid >> 3;                // d-group 0/1
    const int ks = wid & 7;                 // k-slice 0..7
    const int dbase = dg * 8;
    const int kbase = ks * 128;

    // ---- load weight tiles; pre-scale W_h rows by radii[d]/(sigma+eps) ----
    const float sig = fabsf(g_sig_acc) + EPSF;
    for (int i = tid; i < DPC * D / 4; i += NTHR) {
        int idx = i * 4;
        int dd = idx >> 10;
        int k = idx & (D - 1);
        int dglob = d0 + dd;
        *(float4*)(Wx_s + dd * D + k) = *(const float4*)(Wx + (size_t)dglob * D + k);
        float r = (MAXR / (1.f + expf(-logr[dglob]))) / sig;
        float4 m = *(const float4*)(Wh + (size_t)dglob * D + k);
        m.x *= r; m.y *= r; m.z *= r; m.w *= r;
        *(float4*)(Wh_s + dd * D + k) = m;
    }
    __syncthreads();   // weights visible before any smem-weight read

    float* outs_ptr = out;                        // [T][B][D]
    float* hall_ptr = out + (size_t)T * B * D;    // [T+1][B][D]

    // epilogue mapping (tid < 128): consecutive tid -> consecutive d
    const int dl = tid & 15;
    const int bl = (tid >> 4) & 7;
    const size_t eoff = (size_t)(b0 + bl) * D + (d0 + dl);
    const float my_bias = bias[d0 + dl];
    const int epi_p = (dl >> 3) * 32 + (dl & 7) * 4 + (bl >> 1);
    const int epi_half = bl & 1;

    u64 acc[32];

    // ================= PHASE A: precompute pre[t] = x_t Wx^T + b =================
    for (int t = 0; t < T; ++t) {
#pragma unroll
        for (int i = 0; i < 32; ++i) acc[i] = 0ull;
        mv_x(Wx_s, x + (size_t)t * B * D + (size_t)b0 * D, acc, dbase, kbase, lane);
        RED_ALL()
        u64* rb = red_s + (t & 1) * 512;
        rb[ks * 64 + dg * 32 + lane] = acc[0];
        __syncthreads();
        if (tid < 128) {
            u64 s0 = addp(rb[0 * 64 + epi_p], rb[1 * 64 + epi_p]);
            u64 s1 = addp(rb[2 * 64 + epi_p], rb[3 * 64 + epi_p]);
            u64 s2 = addp(rb[4 * 64 + epi_p], rb[5 * 64 + epi_p]);
            u64 s3 = addp(rb[6 * 64 + epi_p], rb[7 * 64 + epi_p]);
            u64 s = addp(addp(s0, s1), addp(s2, s3));
            g_pre[(size_t)t * B * D + eoff] =
                (epi_half ? hi32(s) : lo32(s)) + my_bias;
        }
    }
    __syncthreads();

    // ================= PHASE B: recurrence (Wh GEMV only per step) =================
    volatile unsigned* barp = &g_bar[bg];

    for (int t = 0; t < T; ++t) {
        // prefetch this step's pre and z (independent of barrier)
        float pre_t = 0.f, z_t = 0.f;
        if (tid < 128) {
            pre_t = ldcg(g_pre + (size_t)t * B * D + eoff);
            z_t   = __ldg(z + (size_t)t * B * D + eoff);
        }

        // ---- wait for step t-1 (this batch-half only) ----
        if (t > 0) {
            if (tid == 0) {
                unsigned target = (unsigned)t * HALF;
                while (*barp < target) {}
                __threadfence();
            }
            __syncthreads();
        }

        // ---- stage h_prev: linear coalesced 32 KB copy (coherent L2 path) ----
        {
            const float* hsrc = ((t == 0) ? h0 : g_hbuf[(t - 1) & 1]) + (size_t)b0 * D;
#pragma unroll
            for (int i = 0; i < 4; ++i) {
                int idx = tid + i * NTHR;
                *(float4*)(h_s + idx * 4) = ldcg4((const float4*)(hsrc) + idx);
            }
        }
        __syncthreads();

        // ---- recurrent GEMV ----
#pragma unroll
        for (int i = 0; i < 32; ++i) acc[i] = 0ull;
        mv_smem(Wh_s, h_s, acc, dbase, kbase, lane);
        RED_ALL()
        red_s[ks * 64 + dg * 32 + lane] = acc[0];
        __syncthreads();

        // ---- epilogue (warps 0-3): tanh, publish, gate, arrive ----
        if (tid < 128) {
            u64 s0 = addp(red_s[0 * 64 + epi_p], red_s[1 * 64 + epi_p]);
            u64 s1 = addp(red_s[2 * 64 + epi_p], red_s[3 * 64 + epi_p]);
            u64 s2 = addp(red_s[4 * 64 + epi_p], red_s[5 * 64 + epi_p]);
            u64 s3 = addp(red_s[6 * 64 + epi_p], red_s[7 * 64 + epi_p]);
            u64 s = addp(addp(s0, s1), addp(s2, s3));
            float pre = (epi_half ? hi32(s) : lo32(s)) + pre_t;
            float hnew = tanhf(pre);
            g_hbuf[t & 1][eoff] = hnew;
            float sil = z_t / (1.f + __expf(-z_t));
            outs_ptr[(size_t)t * B * D + eoff] = hnew * sil;
            hall_ptr[(size_t)(t + 1) * B * D + eoff] = hnew;
            asm volatile("bar.sync 1, 128;" ::: "memory");   // epi warps only
            if (tid == 0) {
                __threadfence();
                atomicAdd(&g_bar[bg], 1u);
            }
        }
    }
}

// ---------------- launch ----------------
extern "C" void kernel_launch(void* const* d_in, const int* in_sizes, int n_in,
                              void* d_out, int out_size) {
    const float* x    = (const float*)d_in[0];
    const float* z    = (const float*)d_in[1];
    const float* h0   = (const float*)d_in[2];
    const float* Wx   = (const float*)d_in[3];
    const float* Wh   = (const float*)d_in[4];
    const float* logr = (const float*)d_in[5];
    const float* bias = (const float*)d_in[6];
    const float* u0   = (const float*)d_in[7];
    float* out = (float*)d_out;

    const int smem_bytes = (2 * DPC * D + BPC * D) * (int)sizeof(float)
                         + 1024 * (int)sizeof(u64);
    cudaFuncSetAttribute(k_persist, cudaFuncAttributeMaxDynamicSharedMemorySize,
                         smem_bytes);

    k_init<<<64, 256>>>(h0, out + (size_t)T * B * D);
    k_dot<<<1, 1024>>>(u0);
    for (int p = 0; p < 3; ++p) {
        k_mvT<<<16, 64>>>(Wh, p);
        k_mvN<<<128, 256>>>(Wh, p);
    }
    k_sigma<<<128, 256>>>(Wh);
    k_persist<<<G, NTHR, smem_bytes>>>(x, z, h0, Wx, Wh, logr, bias, out);
}

// round 14
// speedup vs baseline: 1.2590x; 1.0623x over previous
#include <cuda_runtime.h>
#include <math.h>
#include <stdint.h>

#define D     1024
#define B     16
#define T     1024
#define G     128      // persistent CTAs (one per SM)
#define DPC   16       // d's per CTA
#define BPC   8        // b's per CTA
#define NTHR  512      // 16 warps: 2 d-groups (8d) x 8 k-slices (128k)

#define MAXR  0.999f
#define EPSF  1e-8f

typedef unsigned long long u64;

// ---------------- device scratch ----------------
__device__ float    g_hbuf[2][B * D];                 // ping-pong hidden state
__device__ __align__(128) unsigned g_flagv[2][128];   // per-CTA step flags (use [bg][0..63])
__device__ __align__(128) unsigned g_go[2][32];       // per-half go word (use [bg][0])
__device__ float    g_u[D], g_v[D];
__device__ float    g_nu[4], g_nv[4];
__device__ float    g_sig_acc;

// ---------------- packed fp32x2 helpers ----------------
__device__ __forceinline__ u64 dup2(float w) {
    u64 r; asm("mov.b64 %0, {%1, %1};" : "=l"(r) : "f"(w)); return r;
}
__device__ __forceinline__ u64 pack2(float lo, float hi) {
    u64 r; asm("mov.b64 %0, {%1, %2};" : "=l"(r) : "f"(lo), "f"(hi)); return r;
}
__device__ __forceinline__ void fma2(u64& a, u64 w, u64 x) {
    asm("fma.rn.f32x2 %0, %1, %2, %0;" : "+l"(a) : "l"(w), "l"(x));
}
__device__ __forceinline__ u64 addp(u64 a, u64 b) {
    u64 c; asm("add.rn.f32x2 %0, %1, %2;" : "=l"(c) : "l"(a), "l"(b)); return c;
}
__device__ __forceinline__ float lo32(u64 a) { return __uint_as_float((unsigned)(a & 0xffffffffull)); }
__device__ __forceinline__ float hi32(u64 a) { return __uint_as_float((unsigned)(a >> 32)); }

__device__ __forceinline__ float4 ldcg4(const float4* p) {
    float4 v;
    asm volatile("ld.global.cg.v4.f32 {%0,%1,%2,%3}, [%4];"
                 : "=f"(v.x), "=f"(v.y), "=f"(v.z), "=f"(v.w) : "l"(p));
    return v;
}
__device__ __forceinline__ unsigned lda(const unsigned* p) {
    unsigned v;
    asm volatile("ld.acquire.gpu.global.b32 %0, [%1];" : "=r"(v) : "l"(p) : "memory");
    return v;
}

// ---------------- init ----------------
__global__ void k_init(const float* __restrict__ h0, float* __restrict__ hall0) {
    int i = blockIdx.x * blockDim.x + threadIdx.x;
    if (i < 256) ((unsigned*)g_flagv)[i] = 0u;
    if (i < 64)  ((unsigned*)g_go)[i] = 0u;
    if (i < 4) { g_nu[i] = 0.f; g_nv[i] = 0.f; }
    if (i == 4) g_sig_acc = 0.f;
    if (i < B * D) hall0[i] = h0[i];
}

// ---------------- power iteration (distributed, proven) ----------------
__global__ void k_dot(const float* __restrict__ u0) {   // <<<1, 1024>>>
    __shared__ float sred[32];
    int tid = threadIdx.x;
    float v = u0[tid];
    g_u[tid] = v;
    float s = v * v;
#pragma unroll
    for (int m = 16; m; m >>= 1) s += __shfl_xor_sync(0xffffffffu, s, m);
    if ((tid & 31) == 0) sred[tid >> 5] = s;
    __syncthreads();
    if (tid < 32) {
        float r = sred[tid];
#pragma unroll
        for (int m = 16; m; m >>= 1) r += __shfl_xor_sync(0xffffffffu, r, m);
        if (tid == 0) g_nu[0] = r;
    }
}

__global__ void k_mvT(const float* __restrict__ Wh, int p) {   // <<<16, 64>>>
    __shared__ float us[D];
    __shared__ float w2[2];
    int i = blockIdx.x * 64 + threadIdx.x;
    float rs = 1.f / (sqrtf(g_nu[p]) + EPSF);
    for (int j = threadIdx.x; j < D; j += 64) us[j] = g_u[j] * rs;
    __syncthreads();
    float acc = 0.f;
#pragma unroll 8
    for (int j = 0; j < D; ++j) acc += Wh[(size_t)j * D + i] * us[j];
    g_v[i] = acc;
    float s = acc * acc;
#pragma unroll
    for (int m = 16; m; m >>= 1) s += __shfl_xor_sync(0xffffffffu, s, m);
    if ((threadIdx.x & 31) == 0) w2[threadIdx.x >> 5] = s;
    __syncthreads();
    if (threadIdx.x == 0) atomicAdd(&g_nv[p], w2[0] + w2[1]);
}

__global__ void k_mvN(const float* __restrict__ Wh, int p) {   // <<<128, 256>>>
    __shared__ float part[8];
    int wid = threadIdx.x >> 5, lane = threadIdx.x & 31;
    int r = blockIdx.x * 8 + wid;
    float rs = 1.f / (sqrtf(g_nv[p]) + EPSF);
    const float* row = Wh + (size_t)r * D;
    float acc = 0.f;
#pragma unroll
    for (int i = 0; i < 32; ++i) { int j = lane + 32 * i; acc += row[j] * g_v[j]; }
#pragma unroll
    for (int m = 16; m; m >>= 1) acc += __shfl_xor_sync(0xffffffffu, acc, m);
    if (lane == 0) { float u = acc * rs; g_u[r] = u; part[wid] = u * u; }
    __syncthreads();
    if (threadIdx.x == 0) {
        float s = 0.f;
#pragma unroll
        for (int q = 0; q < 8; ++q) s += part[q];
        atomicAdd(&g_nu[p + 1], s);
    }
}

__global__ void k_sigma(const float* __restrict__ Wh) {   // <<<128, 256>>>
    __shared__ float part[8];
    int wid = threadIdx.x >> 5, lane = threadIdx.x & 31;
    int r = blockIdx.x * 8 + wid;
    float rsv = 1.f / (sqrtf(g_nv[2]) + EPSF);
    float rsu = 1.f / (sqrtf(g_nu[3]) + EPSF);
    const float* row = Wh + (size_t)r * D;
    float acc = 0.f;
#pragma unroll
    for (int i = 0; i < 32; ++i) { int j = lane + 32 * i; acc += row[j] * g_v[j]; }
#pragma unroll
    for (int m = 16; m; m >>= 1) acc += __shfl_xor_sync(0xffffffffu, acc, m);
    if (lane == 0) part[wid] = (g_u[r] * rsu) * (acc * rsv);
    __syncthreads();
    if (threadIdx.x == 0) {
        float s = 0.f;
#pragma unroll
        for (int q = 0; q < 8; ++q) s += part[q];
        atomicAdd(&g_sig_acc, s);
    }
}

// ---------------- GEMV tiles: 8d x 8b per warp, 128 k ----------------
__device__ __forceinline__ void mv_x(const float* __restrict__ W,
                                     const float* __restrict__ V,   // gmem [b][D]
                                     u64* __restrict__ acc,
                                     int dbase, int kbase, int lane) {
#pragma unroll
    for (int i = 0; i < 4; ++i) {
        const int k = kbase + 32 * i + lane;
        float v0 = __ldg(V + 0 * D + k), v1 = __ldg(V + 1 * D + k);
        float v2 = __ldg(V + 2 * D + k), v3 = __ldg(V + 3 * D + k);
        float v4 = __ldg(V + 4 * D + k), v5 = __ldg(V + 5 * D + k);
        float v6 = __ldg(V + 6 * D + k), v7 = __ldg(V + 7 * D + k);
        u64 x0 = pack2(v0, v1), x1 = pack2(v2, v3);
        u64 x2 = pack2(v4, v5), x3 = pack2(v6, v7);
#pragma unroll
        for (int dd = 0; dd < 8; ++dd) {
            u64 w = dup2(W[(dbase + dd) * D + k]);
            fma2(acc[dd * 4 + 0], w, x0);
            fma2(acc[dd * 4 + 1], w, x1);
            fma2(acc[dd * 4 + 2], w, x2);
            fma2(acc[dd * 4 + 3], w, x3);
        }
    }
}

__device__ __forceinline__ void mv_smem(const float* __restrict__ W,
                                        const float* __restrict__ V,   // smem [BPC][D]
                                        u64* __restrict__ acc,
                                        int dbase, int kbase, int lane) {
#pragma unroll
    for (int i = 0; i < 4; ++i) {
        const int k = kbase + 32 * i + lane;
        u64 x0 = pack2(V[0 * D + k], V[1 * D + k]);
        u64 x1 = pack2(V[2 * D + k], V[3 * D + k]);
        u64 x2 = pack2(V[4 * D + k], V[5 * D + k]);
        u64 x3 = pack2(V[6 * D + k], V[7 * D + k]);
#pragma unroll
        for (int dd = 0; dd < 8; ++dd) {
            u64 w = dup2(W[(dbase + dd) * D + k]);
            fma2(acc[dd * 4 + 0], w, x0);
            fma2(acc[dd * 4 + 1], w, x1);
            fma2(acc[dd * 4 + 2], w, x2);
            fma2(acc[dd * 4 + 3], w, x3);
        }
    }
}

#define RED_LEVEL(m, n)                                                     \
    {                                                                       \
        const bool up = (lane & (m)) != 0;                                  \
        _Pragma("unroll")                                                   \
        for (int j = 0; j < (n); ++j) {                                     \
            u64 send = up ? acc[j] : acc[j + (n)];                          \
            u64 recv = __shfl_xor_sync(0xffffffffu, send, (m));             \
            acc[j] = addp(up ? acc[j + (n)] : acc[j], recv);                \
        }                                                                   \
    }

#define RED_ALL() RED_LEVEL(16,16) RED_LEVEL(8,8) RED_LEVEL(4,4) RED_LEVEL(2,2) RED_LEVEL(1,1)

// ---------------- persistent fused recurrence ----------------
__global__ void __launch_bounds__(NTHR, 1)
k_persist(const float* __restrict__ x, const float* __restrict__ z,
          const float* __restrict__ h0, const float* __restrict__ Wx,
          const float* __restrict__ Wh, const float* __restrict__ logr,
          const float* __restrict__ bias, float* __restrict__ out) {
    extern __shared__ float sm[];
    float* Wx_s  = sm;                      // [DPC][D]  64 KB
    float* Wh_s  = Wx_s + DPC * D;          // [DPC][D]  64 KB (pre-scaled)
    float* h_s   = Wh_s + DPC * D;          // [BPC][D]  32 KB
    u64*   red_s = (u64*)(h_s + BPC * D);   // [8][64]    4 KB

    const int cta = blockIdx.x;
    const int d0 = (cta >> 1) * DPC;
    const int bg = cta & 1;                 // batch-half group
    const int b0 = bg * BPC;
    const int tid = threadIdx.x;
    const int wid = tid >> 5;
    const int lane = tid & 31;
    const int dg = wid >> 3;                // d-group 0/1
    const int ks = wid & 7;                 // k-slice 0..7
    const int dbase = dg * 8;
    const int kbase = ks * 128;
    const bool is_pub = ((cta >> 1) == 0);  // CTA 0 (bg0) / CTA 1 (bg1) publish

    // ---- load weight tiles; pre-scale W_h rows by radii[d]/(sigma+eps) ----
    const float sig = fabsf(g_sig_acc) + EPSF;
    for (int i = tid; i < DPC * D / 4; i += NTHR) {
        int idx = i * 4;
        int dd = idx >> 10;
        int k = idx & (D - 1);
        int dglob = d0 + dd;
        *(float4*)(Wx_s + dd * D + k) = *(const float4*)(Wx + (size_t)dglob * D + k);
        float r = (MAXR / (1.f + expf(-logr[dglob]))) / sig;
        float4 m = *(const float4*)(Wh + (size_t)dglob * D + k);
        m.x *= r; m.y *= r; m.z *= r; m.w *= r;
        *(float4*)(Wh_s + dd * D + k) = m;
    }
    __syncthreads();   // weights visible before any smem-weight read

    float* outs_ptr = out;                        // [T][B][D]
    float* hall_ptr = out + (size_t)T * B * D;    // [T+1][B][D]

    // epilogue mapping (tid < 128): consecutive tid -> consecutive d
    const int dl = tid & 15;
    const int bl = (tid >> 4) & 7;
    const size_t eoff = (size_t)(b0 + bl) * D + (d0 + dl);
    const float my_bias = bias[d0 + dl];
    const int epi_p = (dl >> 3) * 32 + (dl & 7) * 4 + (bl >> 1);
    const int epi_half = bl & 1;

    u64 acc[32];

    // ---- step 0 x-part (independent of h) ----
#pragma unroll
    for (int i = 0; i < 32; ++i) acc[i] = 0ull;
    mv_x(Wx_s, x + (size_t)b0 * D, acc, dbase, kbase, lane);
    float zreg = (tid < 128) ? __ldg(z + eoff) : 0.f;

    for (int t = 0; t < T; ++t) {
        // ---- barrier: publisher aggregates flags -> go; consumers poll go ----
        if (t > 0) {
            const unsigned tgt = (unsigned)t;
            if (is_pub && wid == 15) {
                unsigned a, b;
                do {
                    a = lda(&g_flagv[bg][lane]);
                    b = lda(&g_flagv[bg][lane + 32]);
                } while (__any_sync(0xffffffffu, (a < tgt) | (b < tgt)));
                if (lane == 0) {
                    __threadfence();
                    *(volatile unsigned*)&g_go[bg][0] = tgt;
                }
                __syncwarp();
            }
            if (tid == 0) {
                while (lda(&g_go[bg][0]) < tgt) {}
                __threadfence();
            }
            __syncthreads();   // sync#1: go broadcast
        }

        // ---- per-warp self-stage: own [8 rows][128 cols] k-block ----
        {
            const float* hsrc = ((t == 0) ? h0 : g_hbuf[(t - 1) & 1]) + (size_t)b0 * D;
#pragma unroll
            for (int r = 0; r < BPC; ++r) {
                float4 v = ldcg4((const float4*)(hsrc + r * D + kbase) + lane);
                *(float4*)(h_s + r * D + kbase + 4 * lane) = v;
            }
            __syncwarp();
        }

        // ---- recurrent GEMV: acc (holds x-part) += W_heff * h_prev ----
        mv_smem(Wh_s, h_s, acc, dbase, kbase, lane);

        // ---- tree reduce: lane L owns acc[L] ----
        RED_ALL()
        red_s[ks * 64 + dg * 32 + lane] = acc[0];
        __syncthreads();   // sync#2: red_s ready

        // ---- epilogue (warps 0-3): tanh, publish, gate, arrive ----
        if (tid < 128) {
            u64 s0 = addp(red_s[0 * 64 + epi_p], red_s[1 * 64 + epi_p]);
            u64 s1 = addp(red_s[2 * 64 + epi_p], red_s[3 * 64 + epi_p]);
            u64 s2 = addp(red_s[4 * 64 + epi_p], red_s[5 * 64 + epi_p]);
            u64 s3 = addp(red_s[6 * 64 + epi_p], red_s[7 * 64 + epi_p]);
            u64 s = addp(addp(s0, s1), addp(s2, s3));
            float pre = (epi_half ? hi32(s) : lo32(s)) + my_bias;
            float hnew = tanhf(pre);
            g_hbuf[t & 1][eoff] = hnew;
            float sil = zreg / (1.f + __expf(-zreg));
            outs_ptr[(size_t)t * B * D + eoff] = hnew * sil;
            hall_ptr[(size_t)(t + 1) * B * D + eoff] = hnew;
            asm volatile("bar.sync 1, 128;" ::: "memory");   // epi warps only
            if (tid == 0) {
                __threadfence();
                *(volatile unsigned*)&g_flagv[bg][cta >> 1] = (unsigned)(t + 1);
            }
        }

        // ---- shadow: x-part of step t+1 (same acc, single reduce next step) ----
#pragma unroll
        for (int i = 0; i < 32; ++i) acc[i] = 0ull;
        if (t + 1 < T) {
            mv_x(Wx_s, x + (size_t)(t + 1) * B * D + (size_t)b0 * D,
                 acc, dbase, kbase, lane);
            if (tid < 128) zreg = __ldg(z + (size_t)(t + 1) * B * D + eoff);
        }
    }
}

// ---------------- launch ----------------
extern "C" void kernel_launch(void* const* d_in, const int* in_sizes, int n_in,
                              void* d_out, int out_size) {
    const float* x    = (const float*)d_in[0];
    const float* z    = (const float*)d_in[1];
    const float* h0   = (const float*)d_in[2];
    const float* Wx   = (const float*)d_in[3];
    const float* Wh   = (const float*)d_in[4];
    const float* logr = (const float*)d_in[5];
    const float* bias = (const float*)d_in[6];
    const float* u0   = (const float*)d_in[7];
    float* out = (float*)d_out;

    const int smem_bytes = (2 * DPC * D + BPC * D) * (int)sizeof(float)
                         + 512 * (int)sizeof(u64);
    cudaFuncSetAttribute(k_persist, cudaFuncAttributeMaxDynamicSharedMemorySize,
                         smem_bytes);

    k_init<<<64, 256>>>(h0, out + (size_t)T * B * D);
    k_dot<<<1, 1024>>>(u0);
    for (int p = 0; p < 3; ++p) {
        k_mvT<<<16, 64>>>(Wh, p);
        k_mvN<<<128, 256>>>(Wh, p);
    }
    k_sigma<<<128, 256>>>(Wh);
    k_persist<<<G, NTHR, smem_bytes>>>(x, z, h0, Wx, Wh, logr, bias, out);
}

// round 16
// speedup vs baseline: 2.1228x; 1.6860x over previous
#include <cuda_runtime.h>
#include <math.h>
#include <stdint.h>

#define D     1024
#define B     16
#define T     1024
#define G     128      // persistent CTAs (one per SM)
#define DPC   16       // d's per CTA
#define BPC   8        // b's per CTA
#define NTHR  512      // 16 warps: 2 d-groups (8d) x 8 k-slices (128k)
#define FSTR  32       // flag stride in u32 (128B line per flag)

#define MAXR  0.999f
#define EPSF  1e-8f

typedef unsigned long long u64;

// ---------------- device scratch ----------------
__device__ float    g_hbuf[2][B * D];                     // ping-pong hidden state
__device__ __align__(128) unsigned g_flagv[2][64 * FSTR]; // per-CTA flag, own 128B line
__device__ float    g_u[D], g_v[D];
__device__ float    g_nu[4], g_nv[4];
__device__ float    g_sig_acc;

// ---------------- packed fp32x2 helpers ----------------
__device__ __forceinline__ u64 dup2(float w) {
    u64 r; asm("mov.b64 %0, {%1, %1};" : "=l"(r) : "f"(w)); return r;
}
__device__ __forceinline__ u64 pack2(float lo, float hi) {
    u64 r; asm("mov.b64 %0, {%1, %2};" : "=l"(r) : "f"(lo), "f"(hi)); return r;
}
__device__ __forceinline__ void fma2(u64& a, u64 w, u64 x) {
    asm("fma.rn.f32x2 %0, %1, %2, %0;" : "+l"(a) : "l"(w), "l"(x));
}
__device__ __forceinline__ u64 addp(u64 a, u64 b) {
    u64 c; asm("add.rn.f32x2 %0, %1, %2;" : "=l"(c) : "l"(a), "l"(b)); return c;
}
__device__ __forceinline__ float lo32(u64 a) { return __uint_as_float((unsigned)(a & 0xffffffffull)); }
__device__ __forceinline__ float hi32(u64 a) { return __uint_as_float((unsigned)(a >> 32)); }

__device__ __forceinline__ float ldcg(const float* p) {
    float v; asm volatile("ld.global.cg.f32 %0, [%1];" : "=f"(v) : "l"(p)); return v;
}
__device__ __forceinline__ unsigned lda(const unsigned* p) {
    unsigned v;
    asm volatile("ld.acquire.gpu.global.b32 %0, [%1];" : "=r"(v) : "l"(p) : "memory");
    return v;
}

// ---------------- init ----------------
__global__ void k_init(const float* __restrict__ h0, float* __restrict__ hall0) {
    int i = blockIdx.x * blockDim.x + threadIdx.x;
    if (i < 2 * 64 * FSTR) ((unsigned*)g_flagv)[i] = 0u;
    if (i < 4) { g_nu[i] = 0.f; g_nv[i] = 0.f; }
    if (i == 4) g_sig_acc = 0.f;
    if (i < B * D) hall0[i] = h0[i];
}

// ---------------- power iteration (distributed, proven) ----------------
__global__ void k_dot(const float* __restrict__ u0) {   // <<<1, 1024>>>
    __shared__ float sred[32];
    int tid = threadIdx.x;
    float v = u0[tid];
    g_u[tid] = v;
    float s = v * v;
#pragma unroll
    for (int m = 16; m; m >>= 1) s += __shfl_xor_sync(0xffffffffu, s, m);
    if ((tid & 31) == 0) sred[tid >> 5] = s;
    __syncthreads();
    if (tid < 32) {
        float r = sred[tid];
#pragma unroll
        for (int m = 16; m; m >>= 1) r += __shfl_xor_sync(0xffffffffu, r, m);
        if (tid == 0) g_nu[0] = r;
    }
}

__global__ void k_mvT(const float* __restrict__ Wh, int p) {   // <<<16, 64>>>
    __shared__ float us[D];
    __shared__ float w2[2];
    int i = blockIdx.x * 64 + threadIdx.x;
    float rs = 1.f / (sqrtf(g_nu[p]) + EPSF);
    for (int j = threadIdx.x; j < D; j += 64) us[j] = g_u[j] * rs;
    __syncthreads();
    float acc = 0.f;
#pragma unroll 8
    for (int j = 0; j < D; ++j) acc += Wh[(size_t)j * D + i] * us[j];
    g_v[i] = acc;
    float s = acc * acc;
#pragma unroll
    for (int m = 16; m; m >>= 1) s += __shfl_xor_sync(0xffffffffu, s, m);
    if ((threadIdx.x & 31) == 0) w2[threadIdx.x >> 5] = s;
    __syncthreads();
    if (threadIdx.x == 0) atomicAdd(&g_nv[p], w2[0] + w2[1]);
}

__global__ void k_mvN(const float* __restrict__ Wh, int p) {   // <<<128, 256>>>
    __shared__ float part[8];
    int wid = threadIdx.x >> 5, lane = threadIdx.x & 31;
    int r = blockIdx.x * 8 + wid;
    float rs = 1.f / (sqrtf(g_nv[p]) + EPSF);
    const float* row = Wh + (size_t)r * D;
    float acc = 0.f;
#pragma unroll
    for (int i = 0; i < 32; ++i) { int j = lane + 32 * i; acc += row[j] * g_v[j]; }
#pragma unroll
    for (int m = 16; m; m >>= 1) acc += __shfl_xor_sync(0xffffffffu, acc, m);
    if (lane == 0) { float u = acc * rs; g_u[r] = u; part[wid] = u * u; }
    __syncthreads();
    if (threadIdx.x == 0) {
        float s = 0.f;
#pragma unroll
        for (int q = 0; q < 8; ++q) s += part[q];
        atomicAdd(&g_nu[p + 1], s);
    }
}

__global__ void k_sigma(const float* __restrict__ Wh) {   // <<<128, 256>>>
    __shared__ float part[8];
    int wid = threadIdx.x >> 5, lane = threadIdx.x & 31;
    int r = blockIdx.x * 8 + wid;
    float rsv = 1.f / (sqrtf(g_nv[2]) + EPSF);
    float rsu = 1.f / (sqrtf(g_nu[3]) + EPSF);
    const float* row = Wh + (size_t)r * D;
    float acc = 0.f;
#pragma unroll
    for (int i = 0; i < 32; ++i) { int j = lane + 32 * i; acc += row[j] * g_v[j]; }
#pragma unroll
    for (int m = 16; m; m >>= 1) acc += __shfl_xor_sync(0xffffffffu, acc, m);
    if (lane == 0) part[wid] = (g_u[r] * rsu) * (acc * rsv);
    __syncthreads();
    if (threadIdx.x == 0) {
        float s = 0.f;
#pragma unroll
        for (int q = 0; q < 8; ++q) s += part[q];
        atomicAdd(&g_sig_acc, s);
    }
}

// ---------------- GEMV tiles: 8d x 8b per warp, 128 k ----------------
// x from GMEM (immutable -> __ldg / NC path)
__device__ __forceinline__ void mv_x(const float* __restrict__ W,
                                     const float* __restrict__ V,   // gmem [b][D]
                                     u64* __restrict__ acc,
                                     int dbase, int kbase, int lane) {
#pragma unroll
    for (int i = 0; i < 4; ++i) {
        const int k = kbase + 32 * i + lane;
        float v0 = __ldg(V + 0 * D + k), v1 = __ldg(V + 1 * D + k);
        float v2 = __ldg(V + 2 * D + k), v3 = __ldg(V + 3 * D + k);
        float v4 = __ldg(V + 4 * D + k), v5 = __ldg(V + 5 * D + k);
        float v6 = __ldg(V + 6 * D + k), v7 = __ldg(V + 7 * D + k);
        u64 x0 = pack2(v0, v1), x1 = pack2(v2, v3);
        u64 x2 = pack2(v4, v5), x3 = pack2(v6, v7);
#pragma unroll
        for (int dd = 0; dd < 8; ++dd) {
            u64 w = dup2(W[(dbase + dd) * D + k]);
            fma2(acc[dd * 4 + 0], w, x0);
            fma2(acc[dd * 4 + 1], w, x1);
            fma2(acc[dd * 4 + 2], w, x2);
            fma2(acc[dd * 4 + 3], w, x3);
        }
    }
}

// h from GMEM via coherent L2 (cross-SM mutable), read directly in the GEMV
__device__ __forceinline__ void mv_h(const float* __restrict__ W,
                                     const float* __restrict__ V,   // gmem [b][D]
                                     u64* __restrict__ acc,
                                     int dbase, int kbase, int lane) {
#pragma unroll
    for (int i = 0; i < 4; ++i) {
        const int k = kbase + 32 * i + lane;
        float v0 = ldcg(V + 0 * D + k), v1 = ldcg(V + 1 * D + k);
        float v2 = ldcg(V + 2 * D + k), v3 = ldcg(V + 3 * D + k);
        float v4 = ldcg(V + 4 * D + k), v5 = ldcg(V + 5 * D + k);
        float v6 = ldcg(V + 6 * D + k), v7 = ldcg(V + 7 * D + k);
        u64 x0 = pack2(v0, v1), x1 = pack2(v2, v3);
        u64 x2 = pack2(v4, v5), x3 = pack2(v6, v7);
#pragma unroll
        for (int dd = 0; dd < 8; ++dd) {
            u64 w = dup2(W[(dbase + dd) * D + k]);
            fma2(acc[dd * 4 + 0], w, x0);
            fma2(acc[dd * 4 + 1], w, x1);
            fma2(acc[dd * 4 + 2], w, x2);
            fma2(acc[dd * 4 + 3], w, x3);
        }
    }
}

#define RED_LEVEL(m, n)                                                     \
    {                                                                       \
        const bool up = (lane & (m)) != 0;                                  \
        _Pragma("unroll")                                                   \
        for (int j = 0; j < (n); ++j) {                                     \
            u64 send = up ? acc[j] : acc[j + (n)];                          \
            u64 recv = __shfl_xor_sync(0xffffffffu, send, (m));             \
            acc[j] = addp(up ? acc[j + (n)] : acc[j], recv);                \
        }                                                                   \
    }

#define RED_ALL() RED_LEVEL(16,16) RED_LEVEL(8,8) RED_LEVEL(4,4) RED_LEVEL(2,2) RED_LEVEL(1,1)

// ---------------- persistent fused recurrence (warp dataflow) ----------------
__global__ void __launch_bounds__(NTHR, 1)
k_persist(const float* __restrict__ x, const float* __restrict__ z,
          const float* __restrict__ h0, const float* __restrict__ Wx,
          const float* __restrict__ Wh, const float* __restrict__ logr,
          const float* __restrict__ bias, float* __restrict__ out) {
    extern __shared__ float sm[];
    float* Wx_s  = sm;                      // [DPC][D]  64 KB
    float* Wh_s  = Wx_s + DPC * D;          // [DPC][D]  64 KB (pre-scaled)
    u64*   red_s = (u64*)(Wh_s + DPC * D);  // [8][64]    4 KB

    const int cta = blockIdx.x;
    const int d0 = (cta >> 1) * DPC;
    const int bg = cta & 1;                 // batch-half group
    const int b0 = bg * BPC;
    const int tid = threadIdx.x;
    const int lane = tid & 31;
    const int wid = tid >> 5;
    const int dg = wid >> 3;                // d-group 0/1
    const int ks = wid & 7;                 // k-slice 0..7
    const int dbase = dg * 8;
    const int kbase = ks * 128;

    // this warp's 8 producer flags (lanes duplicate 4x across the 8 lines)
    const unsigned* myflags = &g_flagv[bg][(unsigned)((ks << 3) + (lane & 7)) * FSTR];

    // ---- load weight tiles; pre-scale W_h rows by radii[d]/(sigma+eps) ----
    const float sig = fabsf(g_sig_acc) + EPSF;
    for (int i = tid; i < DPC * D / 4; i += NTHR) {
        int idx = i * 4;
        int dd = idx >> 10;
        int k = idx & (D - 1);
        int dglob = d0 + dd;
        *(float4*)(Wx_s + dd * D + k) = *(const float4*)(Wx + (size_t)dglob * D + k);
        float r = (MAXR / (1.f + expf(-logr[dglob]))) / sig;
        float4 m = *(const float4*)(Wh + (size_t)dglob * D + k);
        m.x *= r; m.y *= r; m.z *= r; m.w *= r;
        *(float4*)(Wh_s + dd * D + k) = m;
    }
    __syncthreads();   // weights visible before any smem-weight read

    float* outs_ptr = out;                        // [T][B][D]
    float* hall_ptr = out + (size_t)T * B * D;    // [T+1][B][D]

    // epilogue mapping (tid < 128): consecutive tid -> consecutive d
    const int dl = tid & 15;
    const int bl = (tid >> 4) & 7;
    const size_t eoff = (size_t)(b0 + bl) * D + (d0 + dl);
    const float my_bias = bias[d0 + dl];
    const int epi_p = (dl >> 3) * 32 + (dl & 7) * 4 + (bl >> 1);
    const int epi_half = bl & 1;

    u64 acc[32];

    // ---- step 0 x-part (independent of h) ----
#pragma unroll
    for (int i = 0; i < 32; ++i) acc[i] = 0ull;
    mv_x(Wx_s, x + (size_t)b0 * D, acc, dbase, kbase, lane);
    float zreg = (tid < 128) ? __ldg(z + eoff) : 0.f;

    for (int t = 0; t < T; ++t) {
        // ---- per-warp dataflow wait: own 8 producer tiles at step >= t ----
        if (t > 0) {
            const unsigned tgt = (unsigned)t;
            while (__any_sync(0xffffffffu, lda(myflags) < tgt)) {}
        }

        // ---- recurrent GEMV straight from L2 (acquire above orders reads) ----
        const float* hsrc = ((t == 0) ? h0 : g_hbuf[(t - 1) & 1]) + (size_t)b0 * D;
        mv_h(Wh_s, hsrc, acc, dbase, kbase, lane);

        // ---- tree reduce: lane L owns acc[L] ----
        RED_ALL()
        red_s[ks * 64 + dg * 32 + lane] = acc[0];
        __syncthreads();   // sole CTA-wide sync per step

        // ---- epilogue (warps 0-3): tanh, publish h FIRST, release, then outputs ----
        if (tid < 128) {
            u64 s0 = addp(red_s[0 * 64 + epi_p], red_s[1 * 64 + epi_p]);
            u64 s1 = addp(red_s[2 * 64 + epi_p], red_s[3 * 64 + epi_p]);
            u64 s2 = addp(red_s[4 * 64 + epi_p], red_s[5 * 64 + epi_p]);
            u64 s3 = addp(red_s[6 * 64 + epi_p], red_s[7 * 64 + epi_p]);
            u64 s = addp(addp(s0, s1), addp(s2, s3));
            float pre = (epi_half ? hi32(s) : lo32(s)) + my_bias;
            float hnew = tanhf(pre);
            g_hbuf[t & 1][eoff] = hnew;                      // critical store
            asm volatile("bar.sync 1, 128;" ::: "memory");   // epi warps only
            if (tid == 0) {
                __threadfence();
                *(volatile unsigned*)&g_flagv[bg][(unsigned)(cta >> 1) * FSTR] =
                    (unsigned)(t + 1);                       // release
            }
            // non-critical stores after the release
            float sil = zreg / (1.f + __expf(-zreg));
            outs_ptr[(size_t)t * B * D + eoff] = hnew * sil;
            hall_ptr[(size_t)(t + 1) * B * D + eoff] = hnew;
        }

        // ---- shadow: x-part of step t+1 (same acc, single reduce next step) ----
#pragma unroll
        for (int i = 0; i < 32; ++i) acc[i] = 0ull;
        if (t + 1 < T) {
            mv_x(Wx_s, x + (size_t)(t + 1) * B * D + (size_t)b0 * D,
                 acc, dbase, kbase, lane);
            if (tid < 128) zreg = __ldg(z + (size_t)(t + 1) * B * D + eoff);
        }
    }
}

// ---------------- launch ----------------
extern "C" void kernel_launch(void* const* d_in, const int* in_sizes, int n_in,
                              void* d_out, int out_size) {
    const float* x    = (const float*)d_in[0];
    const float* z    = (const float*)d_in[1];
    const float* h0   = (const float*)d_in[2];
    const float* Wx   = (const float*)d_in[3];
    const float* Wh   = (const float*)d_in[4];
    const float* logr = (const float*)d_in[5];
    const float* bias = (const float*)d_in[6];
    const float* u0   = (const float*)d_in[7];
    float* out = (float*)d_out;

    const int smem_bytes = 2 * DPC * D * (int)sizeof(float) + 512 * (int)sizeof(u64);
    cudaFuncSetAttribute(k_persist, cudaFuncAttributeMaxDynamicSharedMemorySize,
                         smem_bytes);

    k_init<<<64, 256>>>(h0, out + (size_t)T * B * D);
    k_dot<<<1, 1024>>>(u0);
    for (int p = 0; p < 3; ++p) {
        k_mvT<<<16, 64>>>(Wh, p);
        k_mvN<<<128, 256>>>(Wh, p);
    }
    k_sigma<<<128, 256>>>(Wh);
    k_persist<<<G, NTHR, smem_bytes>>>(x, z, h0, Wx, Wh, logr, bias, out);
}